// round 16
// baseline (speedup 1.0000x reference)
#include <cuda_runtime.h>
#include <cuda_fp16.h>
#include <cstdint>

#define THREADS 256
#define ROWS 32

// fp16 tile: 32 rows x 128 halves, 256B/row, 16x16B chunks, bank-group swizzle
#define SWH(row, chunk) ((((uint32_t)(row))<<8) | (((((uint32_t)(chunk)) ^ (((uint32_t)(row))&7u)) & 15u)<<4))

// smem: XH(8K) HSH(8K) BH0(8K) BH1(8K) W(32K) W2(32K) = 96KB -> 2 CTAs/SM
#define OFF_XH  0
#define OFF_HSH 8192
#define OFF_BH0 16384
#define OFF_BH1 24576
#define OFF_W   32768
#define OFF_W2  65536
#define SMEM_BYTES 98304

__device__ __half wimg[8][16384];   // Wf,Uf,Wu,Uu,Wi,Ui,Wo,Uo : [n][k] fp16, pre-swizzled image

__device__ __forceinline__ float sigf(float v){
    float t = __expf(-v);
    return __fdividef(1.0f, 1.0f + t);
}
__device__ __forceinline__ float tanhfast(float v){
    v = fminf(fmaxf(v, -15.0f), 15.0f);
    float t = __expf(-2.0f*v);
    return __fdividef(1.0f - t, 1.0f + t);
}
__device__ __forceinline__ void cpa16(uint32_t s, const void* g){
    asm volatile("cp.async.cg.shared.global [%0], [%1], 16;\n" :: "r"(s), "l"(g));
}
#define CP_COMMIT() asm volatile("cp.async.commit_group;\n" ::: "memory")
#define CP_WAIT(n)  asm volatile("cp.async.wait_group %0;\n" :: "n"(n) : "memory")

// 32KB fp16 weight image (pre-swizzled) -> linear copy
__device__ __forceinline__ void cpa_w(uint32_t sdst, const __half* __restrict__ src, int tid){
    const char* s = (const char*)src;
    #pragma unroll
    for (int i=0;i<8;i++){
        int idx = tid + i*THREADS;
        cpa16(sdst + (uint32_t)idx*16u, s + (size_t)idx*16);
    }
}

__device__ __forceinline__ void ldsm4(uint32_t* d, uint32_t saddr){
    asm volatile("ldmatrix.sync.aligned.m8n8.x4.shared.b16 {%0,%1,%2,%3}, [%4];\n"
      : "=r"(d[0]),"=r"(d[1]),"=r"(d[2]),"=r"(d[3]) : "r"(saddr));
}
__device__ __forceinline__ void mma16(float* c, const uint32_t* a, uint32_t b0, uint32_t b1){
    asm volatile(
      "mma.sync.aligned.m16n8k16.row.col.f32.f16.f16.f32 "
      "{%0,%1,%2,%3},{%4,%5,%6,%7},{%8,%9},{%0,%1,%2,%3};\n"
      : "+f"(c[0]),"+f"(c[1]),"+f"(c[2]),"+f"(c[3])
      : "r"(a[0]),"r"(a[1]),"r"(a[2]),"r"(a[3]), "r"(b0),"r"(b1));
}

// 32x128x128 fp16 GEMM (f32 accum); 8 warps as 2(m) x 4(n); warp tile 16x32.
__device__ __forceinline__ void gemm32h(float (&acc)[4][4], uint32_t Ab, uint32_t Bb,
                                        int lane, int wm, int wn)
{
    uint32_t lrow = (lane&7) + ((lane>>3)&1)*8;
    uint32_t csel = (lane>>4)&1;
    uint32_t arow = wm*16 + lrow;
    uint32_t abase = Ab + (arow<<8);
    uint32_t axor  = arow & 7u;
    uint32_t brow = wn*32 + lrow;
    uint32_t bxor  = brow & 7u;
    uint32_t bb0 = Bb + (brow<<8);
    uint32_t bb1 = bb0 + (16u<<8);

    #pragma unroll
    for (int kk=0;kk<8;kk++){
        uint32_t a[4], b0[4], b1[4];
        uint32_t ac = ((uint32_t)(kk*2 + csel) ^ axor) << 4;
        uint32_t bc = ((uint32_t)(kk*2 + csel) ^ bxor) << 4;
        ldsm4(a,  abase + ac);
        ldsm4(b0, bb0 + bc);
        ldsm4(b1, bb1 + bc);
        mma16(acc[0], a, b0[0], b0[2]);
        mma16(acc[1], a, b0[1], b0[3]);
        mma16(acc[2], a, b1[0], b1[2]);
        mma16(acc[3], a, b1[1], b1[3]);
    }
}

#define ZERO_ACC(A) { _Pragma("unroll") for(int _n=0;_n<4;_n++) _Pragma("unroll") for(int _e=0;_e<4;_e++) (A)[_n][_e]=0.0f; }

// ---- prep: transpose + fp16-round + swizzle all 8 weight matrices ------
__global__ void prep_weights(const float* __restrict__ Wf, const float* __restrict__ Uf,
                             const float* __restrict__ Wu, const float* __restrict__ Uu,
                             const float* __restrict__ Wi, const float* __restrict__ Ui,
                             const float* __restrict__ Wo, const float* __restrict__ Uo)
{
    const float* srcs[8] = {Wf,Uf,Wu,Uu,Wi,Ui,Wo,Uo};
    const float* s = srcs[blockIdx.x];
    __half* d = wimg[blockIdx.x];
    for (int i = threadIdx.x; i < 128*128; i += blockDim.x){
        int n = i >> 7, k = i & 127;
        int idx = n*128 + ((((k>>3) ^ (n&7)) & 15) << 3) + (k & 7);
        d[idx] = __float2half_rn(s[k*128 + n]);   // B[n][k] = W[k][n]
    }
}

__global__ void __launch_bounds__(THREADS, 2)
treelstm_kernel(const float* __restrict__ x,
                const float* __restrict__ child_h,
                const float* __restrict__ child_c,
                const float* __restrict__ bi, const float* __restrict__ bo,
                const float* __restrict__ bu, const float* __restrict__ bf,
                float* __restrict__ out, int N)
{
    extern __shared__ char smem[];
    uint32_t sb;
    asm("{ .reg .u64 t; cvta.to.shared.u64 t, %1; cvt.u32.u64 %0, t; }" : "=r"(sb) : "l"(smem));
    const uint32_t XHb  = sb + OFF_XH;
    const uint32_t HSHb = sb + OFF_HSH;
    const uint32_t Wa   = sb + OFF_W;
    const uint32_t Wb2  = sb + OFF_W2;

    const int tid  = threadIdx.x;
    const int lane = tid & 31;
    const int g    = lane >> 2;
    const int r    = lane & 3;
    const int wid  = tid >> 5;
    const int wm   = wid & 1;           // 16-row half
    const int wn   = wid >> 1;          // 32-col group
    const int m0   = blockIdx.x * ROWS;

    const int Rr   = wm*16 + g;         // owned rows: Rr, Rr+8 (tile-local)
    const int Rg   = m0 + Rr;           // global rows

    // per-nt column C0 = wn*32 + nt*8 + 2*r ; fp16 smem addr pieces
    // ckh = C0>>3, inner = (C0&7)*2

    float acc [4][4];
    float cacc[4][4];
    float xfv [4][4];   // xf during children, u during gates
    float hs  [4][4];

    #pragma unroll
    for (int nt=0;nt<4;nt++)
      #pragma unroll
      for (int e=0;e<4;e++){ cacc[nt][e]=0.f; hs[nt][e]=0.f; }

    // ---- prologue -------------------------------------------------------
    cpa_w(Wa, wimg[0], tid); CP_COMMIT();            // Wf
    // x slice: LDG + convert -> XH
    #pragma unroll
    for (int nt=0;nt<4;nt++){
        int C0 = wn*32 + nt*8 + 2*r;
        int ckh = C0>>3, inh = (C0&7)<<1;
        float2 v0 = __ldg(reinterpret_cast<const float2*>(x + (size_t)Rg*128 + C0));
        float2 v1 = __ldg(reinterpret_cast<const float2*>(x + (size_t)(Rg+8)*128 + C0));
        *reinterpret_cast<__half2*>(smem + OFF_XH + SWH(Rr,   ckh) + inh) = __floats2half2_rn(v0.x, v0.y);
        *reinterpret_cast<__half2*>(smem + OFF_XH + SWH(Rr+8, ckh) + inh) = __floats2half2_rn(v1.x, v1.y);
    }
    // issue ch0 loads
    float2 ch0[4], ch1[4];
    #pragma unroll
    for (int nt=0;nt<4;nt++){
        int C0 = wn*32 + nt*8 + 2*r;
        ch0[nt] = __ldg(reinterpret_cast<const float2*>(child_h + ((size_t)Rg    *8 + 0)*128 + C0));
        ch1[nt] = __ldg(reinterpret_cast<const float2*>(child_h + ((size_t)(Rg+8)*8 + 0)*128 + C0));
    }

    CP_WAIT(0); __syncthreads();                     // Wf + XH visible

    // ---- phase 1: xf = x @ Wf + bf ---------------------------------------
    ZERO_ACC(acc);
    gemm32h(acc, XHb, Wa, lane, wm, wn);
    __syncthreads();                                 // Wa free
    cpa_w(Wa, wimg[1], tid); CP_COMMIT();            // Uf

    #pragma unroll
    for (int nt=0;nt<4;nt++){
        int C0 = wn*32 + nt*8 + 2*r;
        float2 bv = *reinterpret_cast<const float2*>(bf + C0);
        xfv[nt][0] = acc[nt][0] + bv.x;
        xfv[nt][1] = acc[nt][1] + bv.y;
        xfv[nt][2] = acc[nt][2] + bv.x;
        xfv[nt][3] = acc[nt][3] + bv.y;
    }

    // consume ch(0): hs += raw, STS fp16 -> BH0 ; issue ch(1), cc(0)
    float2 cc0[4], cc1[4];
    #pragma unroll
    for (int nt=0;nt<4;nt++){
        int C0 = wn*32 + nt*8 + 2*r;
        int ckh = C0>>3, inh = (C0&7)<<1;
        hs[nt][0] += ch0[nt].x; hs[nt][1] += ch0[nt].y;
        hs[nt][2] += ch1[nt].x; hs[nt][3] += ch1[nt].y;
        *reinterpret_cast<__half2*>(smem + OFF_BH0 + SWH(Rr,   ckh) + inh) = __floats2half2_rn(ch0[nt].x, ch0[nt].y);
        *reinterpret_cast<__half2*>(smem + OFF_BH0 + SWH(Rr+8, ckh) + inh) = __floats2half2_rn(ch1[nt].x, ch1[nt].y);
        ch0[nt] = __ldg(reinterpret_cast<const float2*>(child_h + ((size_t)Rg    *8 + 1)*128 + C0));
        ch1[nt] = __ldg(reinterpret_cast<const float2*>(child_h + ((size_t)(Rg+8)*8 + 1)*128 + C0));
        cc0[nt] = __ldg(reinterpret_cast<const float2*>(child_c + ((size_t)Rg    *8 + 0)*128 + C0));
        cc1[nt] = __ldg(reinterpret_cast<const float2*>(child_c + ((size_t)(Rg+8)*8 + 0)*128 + C0));
    }

    CP_WAIT(0); __syncthreads();                     // Uf + BH0 visible

    // ---- phase 2: children; one barrier per iteration --------------------
    #pragma unroll 1
    for (int k=0;k<8;k++){
        const uint32_t BHcur = sb + (uint32_t)((k&1) ? OFF_BH1 : OFF_BH0);
        const int      BHnxt = (k&1) ? OFF_BH0 : OFF_BH1;

        // consume ch(k+1) -> hs + BHnxt ; issue ch(k+2), cc(k+1)
        float2 nc0[4], nc1[4];
        if (k < 7){
            #pragma unroll
            for (int nt=0;nt<4;nt++){
                int C0 = wn*32 + nt*8 + 2*r;
                int ckh = C0>>3, inh = (C0&7)<<1;
                hs[nt][0] += ch0[nt].x; hs[nt][1] += ch0[nt].y;
                hs[nt][2] += ch1[nt].x; hs[nt][3] += ch1[nt].y;
                *reinterpret_cast<__half2*>(smem + BHnxt + SWH(Rr,   ckh) + inh) = __floats2half2_rn(ch0[nt].x, ch0[nt].y);
                *reinterpret_cast<__half2*>(smem + BHnxt + SWH(Rr+8, ckh) + inh) = __floats2half2_rn(ch1[nt].x, ch1[nt].y);
            }
            if (k < 6){
                #pragma unroll
                for (int nt=0;nt<4;nt++){
                    int C0 = wn*32 + nt*8 + 2*r;
                    ch0[nt] = __ldg(reinterpret_cast<const float2*>(child_h + ((size_t)Rg    *8 + (k+2))*128 + C0));
                    ch1[nt] = __ldg(reinterpret_cast<const float2*>(child_h + ((size_t)(Rg+8)*8 + (k+2))*128 + C0));
                }
            }
            #pragma unroll
            for (int nt=0;nt<4;nt++){
                int C0 = wn*32 + nt*8 + 2*r;
                nc0[nt] = __ldg(reinterpret_cast<const float2*>(child_c + ((size_t)Rg    *8 + (k+1))*128 + C0));
                nc1[nt] = __ldg(reinterpret_cast<const float2*>(child_c + ((size_t)(Rg+8)*8 + (k+1))*128 + C0));
            }
        }

        // gemm ch_k @ Uf
        ZERO_ACC(acc);
        gemm32h(acc, BHcur, Wa, lane, wm, wn);

        // epilogue with cc(k)
        #pragma unroll
        for (int nt=0;nt<4;nt++){
            cacc[nt][0] += sigf(xfv[nt][0] + acc[nt][0]) * cc0[nt].x;
            cacc[nt][1] += sigf(xfv[nt][1] + acc[nt][1]) * cc0[nt].y;
            cacc[nt][2] += sigf(xfv[nt][2] + acc[nt][2]) * cc1[nt].x;
            cacc[nt][3] += sigf(xfv[nt][3] + acc[nt][3]) * cc1[nt].y;
        }
        if (k < 7){
            #pragma unroll
            for (int nt=0;nt<4;nt++){ cc0[nt] = nc0[nt]; cc1[nt] = nc1[nt]; }
        }

        __syncthreads();    // BHnxt visible for k+1; protects BH reuse at k+2
    }

    // ---- gate prologue: hs -> HSH (fp16); weight ping-pong ----------------
    #pragma unroll
    for (int nt=0;nt<4;nt++){
        int C0 = wn*32 + nt*8 + 2*r;
        int ckh = C0>>3, inh = (C0&7)<<1;
        *reinterpret_cast<__half2*>(smem + OFF_HSH + SWH(Rr,   ckh) + inh) = __floats2half2_rn(hs[nt][0], hs[nt][1]);
        *reinterpret_cast<__half2*>(smem + OFF_HSH + SWH(Rr+8, ckh) + inh) = __floats2half2_rn(hs[nt][2], hs[nt][3]);
    }
    __syncthreads();                                 // last gemm done (Wa free); HSH visible
    cpa_w(Wa,  wimg[2], tid); CP_COMMIT();           // Wu
    cpa_w(Wb2, wimg[3], tid); CP_COMMIT();           // Uu

    const float* bs[3] = {bu, bi, bo};

    // ---- phase 3: 6 weight steps (Wu,Uu,Wi,Ui,Wo,Uo), 2-deep pipeline -----
    #pragma unroll 1
    for (int j=0;j<6;j++){
        const uint32_t buf = (j&1) ? Wb2 : Wa;
        if (j<5) { CP_WAIT(1); } else { CP_WAIT(0); }
        __syncthreads();                             // weight j visible
        if ((j&1)==0){
            ZERO_ACC(acc);
            gemm32h(acc, XHb, buf, lane, wm, wn);    // x @ W_g
        } else {
            gemm32h(acc, HSHb, buf, lane, wm, wn);   // + hs @ U_g
        }
        __syncthreads();                             // buf free
        if (j+2 < 6){ cpa_w(buf, wimg[2 + j + 2], tid); CP_COMMIT(); }

        if (j&1){
            const int gate = j>>1;
            const float* bp = bs[gate];
            #pragma unroll
            for (int nt=0;nt<4;nt++){
                int C0 = wn*32 + nt*8 + 2*r;
                float2 bv = *reinterpret_cast<const float2*>(bp + C0);
                float p0 = acc[nt][0] + bv.x;
                float p1 = acc[nt][1] + bv.y;
                float p2 = acc[nt][2] + bv.x;
                float p3 = acc[nt][3] + bv.y;
                if (gate == 0){
                    xfv[nt][0] = tanhfast(p0);
                    xfv[nt][1] = tanhfast(p1);
                    xfv[nt][2] = tanhfast(p2);
                    xfv[nt][3] = tanhfast(p3);
                } else if (gate == 1){
                    cacc[nt][0] += sigf(p0) * xfv[nt][0];
                    cacc[nt][1] += sigf(p1) * xfv[nt][1];
                    cacc[nt][2] += sigf(p2) * xfv[nt][2];
                    cacc[nt][3] += sigf(p3) * xfv[nt][3];
                } else {
                    float c0 = cacc[nt][0], c1 = cacc[nt][1];
                    float c2 = cacc[nt][2], c3 = cacc[nt][3];
                    float h0 = sigf(p0) * tanhfast(c0);
                    float h1 = sigf(p1) * tanhfast(c1);
                    float h2 = sigf(p2) * tanhfast(c2);
                    float h3 = sigf(p3) * tanhfast(c3);
                    float* outh = out;
                    float* outc = out + (size_t)N*128;
                    *reinterpret_cast<float2*>(outh + (size_t) Rg   *128 + C0) = make_float2(h0,h1);
                    *reinterpret_cast<float2*>(outh + (size_t)(Rg+8)*128 + C0) = make_float2(h2,h3);
                    *reinterpret_cast<float2*>(outc + (size_t) Rg   *128 + C0) = make_float2(c0,c1);
                    *reinterpret_cast<float2*>(outc + (size_t)(Rg+8)*128 + C0) = make_float2(c2,c3);
                }
            }
        }
    }
}

extern "C" void kernel_launch(void* const* d_in, const int* in_sizes, int n_in,
                              void* d_out, int out_size)
{
    const float* x       = (const float*)d_in[0];
    const float* child_h = (const float*)d_in[1];
    const float* child_c = (const float*)d_in[2];
    const float* Wi = (const float*)d_in[3];
    const float* bi = (const float*)d_in[4];
    const float* Ui = (const float*)d_in[5];
    const float* Wo = (const float*)d_in[6];
    const float* bo = (const float*)d_in[7];
    const float* Uo = (const float*)d_in[8];
    const float* Wu = (const float*)d_in[9];
    const float* bu = (const float*)d_in[10];
    const float* Uu = (const float*)d_in[11];
    const float* Wf = (const float*)d_in[12];
    const float* bf = (const float*)d_in[13];
    const float* Uf = (const float*)d_in[14];
    float* out = (float*)d_out;

    int N = in_sizes[0] / 128;
    int blocks = N / ROWS;

    prep_weights<<<8, 256>>>(Wf, Uf, Wu, Uu, Wi, Ui, Wo, Uo);

    cudaFuncSetAttribute(treelstm_kernel,
                         cudaFuncAttributeMaxDynamicSharedMemorySize, SMEM_BYTES);
    treelstm_kernel<<<blocks, THREADS, SMEM_BYTES>>>(
        x, child_h, child_c, bi, bo, bu, bf, out, N);
}

// round 17
// speedup vs baseline: 1.2979x; 1.2979x over previous
#include <cuda_runtime.h>
#include <cuda_fp16.h>
#include <cstdint>

#define THREADS 256
#define ROWS 32

// f32 staging tile: 32 rows x 128 f32, 512B/row, 32x16B chunks, bank-group swizzle
#define SWF(row, chunk) ((((uint32_t)(row))<<9) | (((((uint32_t)(chunk)) ^ (((uint32_t)(row))&7u)) & 31u)<<4))
// fp16 tile: rows x 128 halves, 256B/row, 16x16B chunks
#define SWH(row, chunk) ((((uint32_t)(row))<<8) | (((((uint32_t)(chunk)) ^ (((uint32_t)(row))&7u)) & 15u)<<4))

// smem: XH(8K) HSH(8K) BH0(8K) BH1(8K) B0(16K) B1(16K) W(32K) = 96KB -> 2 CTAs/SM
// gate phase: WP aliases B0+B1 (32K contiguous) as weight pong buffer
#define OFF_XH  0
#define OFF_HSH 8192
#define OFF_BH0 16384
#define OFF_BH1 24576
#define OFF_B0  32768
#define OFF_B1  49152
#define OFF_W   65536
#define SMEM_BYTES 98304

__device__ __half wimg[8][16384];   // Wf,Uf,Wu,Uu,Wi,Ui,Wo,Uo : [n][k] fp16, pre-swizzled image

__device__ __forceinline__ float sigf(float v){
    float t = __expf(-v);
    return __fdividef(1.0f, 1.0f + t);
}
__device__ __forceinline__ float tanhfast(float v){
    v = fminf(fmaxf(v, -15.0f), 15.0f);
    float t = __expf(-2.0f*v);
    return __fdividef(1.0f - t, 1.0f + t);
}
__device__ __forceinline__ void cpa16(uint32_t s, const void* g){
    asm volatile("cp.async.cg.shared.global [%0], [%1], 16;\n" :: "r"(s), "l"(g));
}
#define CP_COMMIT() asm volatile("cp.async.commit_group;\n" ::: "memory")
#define CP_WAIT(n)  asm volatile("cp.async.wait_group %0;\n" :: "n"(n) : "memory")

// 32-row x 128-col f32 tile -> swizzled staging
__device__ __forceinline__ void cpa_t32(uint32_t sdst, const float* __restrict__ src,
                                        int rs, int tid){
    #pragma unroll
    for (int i=0;i<4;i++){
        int e = tid + i*THREADS;
        int row = e >> 5, c = e & 31;
        cpa16(sdst + SWF(row, c), src + (size_t)row*rs + c*4);
    }
}
// 32KB fp16 weight image (pre-swizzled) -> linear copy
__device__ __forceinline__ void cpa_w(uint32_t sdst, const __half* __restrict__ src, int tid){
    const char* s = (const char*)src;
    #pragma unroll
    for (int i=0;i<8;i++){
        int idx = tid + i*THREADS;
        cpa16(sdst + (uint32_t)idx*16u, s + (size_t)idx*16);
    }
}

__device__ __forceinline__ void ldsm4(uint32_t* d, uint32_t saddr){
    asm volatile("ldmatrix.sync.aligned.m8n8.x4.shared.b16 {%0,%1,%2,%3}, [%4];\n"
      : "=r"(d[0]),"=r"(d[1]),"=r"(d[2]),"=r"(d[3]) : "r"(saddr));
}
__device__ __forceinline__ void mma16(float* c, const uint32_t* a, uint32_t b0, uint32_t b1){
    asm volatile(
      "mma.sync.aligned.m16n8k16.row.col.f32.f16.f16.f32 "
      "{%0,%1,%2,%3},{%4,%5,%6,%7},{%8,%9},{%0,%1,%2,%3};\n"
      : "+f"(c[0]),"+f"(c[1]),"+f"(c[2]),"+f"(c[3])
      : "r"(a[0]),"r"(a[1]),"r"(a[2]),"r"(a[3]), "r"(b0),"r"(b1));
}

// 32x128x128 fp16 GEMM (f32 accum); 8 warps as 2(m) x 4(n); warp tile 16x32.
__device__ __forceinline__ void gemm32h(float (&acc)[4][4], uint32_t Ab, uint32_t Bb,
                                        int lane, int wm, int wn)
{
    uint32_t lrow = (lane&7) + ((lane>>3)&1)*8;
    uint32_t csel = (lane>>4)&1;
    uint32_t arow = wm*16 + lrow;
    uint32_t abase = Ab + (arow<<8);
    uint32_t axor  = arow & 7u;
    uint32_t brow = wn*32 + lrow;
    uint32_t bxor  = brow & 7u;
    uint32_t bb0 = Bb + (brow<<8);
    uint32_t bb1 = bb0 + (16u<<8);

    #pragma unroll
    for (int kk=0;kk<8;kk++){
        uint32_t a[4], b0[4], b1[4];
        uint32_t ac = ((uint32_t)(kk*2 + csel) ^ axor) << 4;
        uint32_t bc = ((uint32_t)(kk*2 + csel) ^ bxor) << 4;
        ldsm4(a,  abase + ac);
        ldsm4(b0, bb0 + bc);
        ldsm4(b1, bb1 + bc);
        mma16(acc[0], a, b0[0], b0[2]);
        mma16(acc[1], a, b0[1], b0[3]);
        mma16(acc[2], a, b1[0], b1[2]);
        mma16(acc[3], a, b1[1], b1[3]);
    }
}

#define ZERO_ACC(A) { _Pragma("unroll") for(int _n=0;_n<4;_n++) _Pragma("unroll") for(int _e=0;_e<4;_e++) (A)[_n][_e]=0.0f; }

// ---- prep: transpose + fp16-round + swizzle all 8 weight matrices ------
__global__ void prep_weights(const float* __restrict__ Wf, const float* __restrict__ Uf,
                             const float* __restrict__ Wu, const float* __restrict__ Uu,
                             const float* __restrict__ Wi, const float* __restrict__ Ui,
                             const float* __restrict__ Wo, const float* __restrict__ Uo)
{
    const float* srcs[8] = {Wf,Uf,Wu,Uu,Wi,Ui,Wo,Uo};
    const float* s = srcs[blockIdx.x];
    __half* d = wimg[blockIdx.x];
    for (int i = threadIdx.x; i < 128*128; i += blockDim.x){
        int n = i >> 7, k = i & 127;
        int idx = n*128 + ((((k>>3) ^ (n&7)) & 15) << 3) + (k & 7);
        d[idx] = __float2half_rn(s[k*128 + n]);   // B[n][k] = W[k][n]
    }
}

__global__ void __launch_bounds__(THREADS, 2)
treelstm_kernel(const float* __restrict__ x,
                const float* __restrict__ child_h,
                const float* __restrict__ child_c,
                const float* __restrict__ bi, const float* __restrict__ bo,
                const float* __restrict__ bu, const float* __restrict__ bf,
                float* __restrict__ out, int N)
{
    extern __shared__ char smem[];
    uint32_t sb;
    asm("{ .reg .u64 t; cvta.to.shared.u64 t, %1; cvt.u32.u64 %0, t; }" : "=r"(sb) : "l"(smem));
    const uint32_t XHb  = sb + OFF_XH;
    const uint32_t HSHb = sb + OFF_HSH;
    const uint32_t B0b  = sb + OFF_B0;
    const uint32_t B1b  = sb + OFF_B1;
    const uint32_t Wa   = sb + OFF_W;
    const uint32_t WP   = sb + OFF_B0;   // gate-phase pong buffer (aliases B0+B1)

    const int tid  = threadIdx.x;
    const int lane = tid & 31;
    const int g    = lane >> 2;
    const int r    = lane & 3;
    const int wid  = tid >> 5;
    const int wm   = wid & 1;           // 16-row half
    const int wn   = wid >> 1;          // 32-col group
    const int m0   = blockIdx.x * ROWS;

    const int Rr   = wm*16 + g;         // owned rows: Rr, Rr+8 (tile-local)
    const int Rg   = m0 + Rr;           // global rows

    float acc [4][4];
    float cacc[4][4];
    float xfv [4][4];   // xf during children, u during gates
    float hs  [4][4];

    #pragma unroll
    for (int nt=0;nt<4;nt++)
      #pragma unroll
      for (int e=0;e<4;e++){ cacc[nt][e]=0.f; hs[nt][e]=0.f; }

    // ---- prologue: G1{Wf, x->B0} G2{ch0->B1} ----------------------------
    cpa_w  (Wa, wimg[0], tid);
    cpa_t32(B0b, x + (size_t)m0*128, 128, tid);
    CP_COMMIT();                                     // G1
    cpa_t32(B1b, child_h + ((size_t)m0*8 + 0)*128, 8*128, tid);
    CP_COMMIT();                                     // G2

    CP_WAIT(1); __syncthreads();                     // Wf + x staged
    // convert x slice -> XH (fp16)
    #pragma unroll
    for (int nt=0;nt<4;nt++){
        int C0 = wn*32 + nt*8 + 2*r;
        int ckf = C0>>2, inf = (C0&3)<<2;
        int ckh = C0>>3, inh = (C0&7)<<1;
        float2 v0 = *reinterpret_cast<const float2*>(smem + OFF_B0 + SWF(Rr,   ckf) + inf);
        float2 v1 = *reinterpret_cast<const float2*>(smem + OFF_B0 + SWF(Rr+8, ckf) + inf);
        *reinterpret_cast<__half2*>(smem + OFF_XH + SWH(Rr,   ckh) + inh) = __floats2half2_rn(v0.x, v0.y);
        *reinterpret_cast<__half2*>(smem + OFF_XH + SWH(Rr+8, ckh) + inh) = __floats2half2_rn(v1.x, v1.y);
    }
    __syncthreads();                                 // XH visible

    // ---- phase 1: xf = x @ Wf + bf ---------------------------------------
    ZERO_ACC(acc);
    gemm32h(acc, XHb, Wa, lane, wm, wn);
    __syncthreads();                                 // Wa + B0 free
    cpa_w  (Wa, wimg[1], tid);                       // Uf
    cpa_t32(B0b, child_h + ((size_t)m0*8 + 1)*128, 8*128, tid);  // ch1
    CP_COMMIT();                                     // G3

    #pragma unroll
    for (int nt=0;nt<4;nt++){
        int C0 = wn*32 + nt*8 + 2*r;
        float2 bv = *reinterpret_cast<const float2*>(bf + C0);
        xfv[nt][0] = acc[nt][0] + bv.x;
        xfv[nt][1] = acc[nt][1] + bv.y;
        xfv[nt][2] = acc[nt][2] + bv.x;
        xfv[nt][3] = acc[nt][3] + bv.y;
    }

    // convert ch0 (B1 staged since G2) -> BH0, hs +=
    CP_WAIT(1);                                      // G2 done (G3 outstanding)
    __syncthreads();
    #pragma unroll
    for (int nt=0;nt<4;nt++){
        int C0 = wn*32 + nt*8 + 2*r;
        int ckf = C0>>2, inf = (C0&3)<<2;
        int ckh = C0>>3, inh = (C0&7)<<1;
        float2 v0 = *reinterpret_cast<const float2*>(smem + OFF_B1 + SWF(Rr,   ckf) + inf);
        float2 v1 = *reinterpret_cast<const float2*>(smem + OFF_B1 + SWF(Rr+8, ckf) + inf);
        hs[nt][0] += v0.x; hs[nt][1] += v0.y;
        hs[nt][2] += v1.x; hs[nt][3] += v1.y;
        *reinterpret_cast<__half2*>(smem + OFF_BH0 + SWH(Rr,   ckh) + inh) = __floats2half2_rn(v0.x, v0.y);
        *reinterpret_cast<__half2*>(smem + OFF_BH0 + SWH(Rr+8, ckh) + inh) = __floats2half2_rn(v1.x, v1.y);
    }
    CP_WAIT(0); __syncthreads();                     // Uf + ch1 staged; BH0 visible

    // ---- phase 2: children, ONE barrier per iteration --------------------
    // invariants at top of iter k: BH(k) ready; ch(k+1) staged in S(k+1) (k<7)
    // S(j) = B0 if j odd, B1 if j even
    #pragma unroll 1
    for (int k=0;k<8;k++){
        const uint32_t BHcur = sb + (uint32_t)((k&1) ? OFF_BH1 : OFF_BH0);
        const int      BHnxt = (k&1) ? OFF_BH0 : OFF_BH1;

        // issue ch(k+2) into S(k+2) (freed by convert at iter k-1, sync'd)
        if (k+2 <= 7){
            uint32_t sdst = ((k+2)&1) ? B0b : B1b;
            cpa_t32(sdst, child_h + ((size_t)m0*8 + (k+2))*128, 8*128, tid);
            CP_COMMIT();
        }
        // convert ch(k+1) -> BHnxt, hs +=
        if (k < 7){
            int stgOff = ((k+1)&1) ? OFF_B0 : OFF_B1;
            #pragma unroll
            for (int nt=0;nt<4;nt++){
                int C0 = wn*32 + nt*8 + 2*r;
                int ckf = C0>>2, inf = (C0&3)<<2;
                int ckh = C0>>3, inh = (C0&7)<<1;
                float2 v0 = *reinterpret_cast<const float2*>(smem + stgOff + SWF(Rr,   ckf) + inf);
                float2 v1 = *reinterpret_cast<const float2*>(smem + stgOff + SWF(Rr+8, ckf) + inf);
                hs[nt][0] += v0.x; hs[nt][1] += v0.y;
                hs[nt][2] += v1.x; hs[nt][3] += v1.y;
                *reinterpret_cast<__half2*>(smem + BHnxt + SWH(Rr,   ckh) + inh) = __floats2half2_rn(v0.x, v0.y);
                *reinterpret_cast<__half2*>(smem + BHnxt + SWH(Rr+8, ckh) + inh) = __floats2half2_rn(v1.x, v1.y);
            }
        }
        // prefetch child_c[k]
        float2 cc0[4], cc1[4];
        #pragma unroll
        for (int nt=0;nt<4;nt++){
            int C0 = wn*32 + nt*8 + 2*r;
            cc0[nt] = __ldg(reinterpret_cast<const float2*>(child_c + ((size_t)Rg    *8 + k)*128 + C0));
            cc1[nt] = __ldg(reinterpret_cast<const float2*>(child_c + ((size_t)(Rg+8)*8 + k)*128 + C0));
        }

        // gemm ch_k @ Uf
        ZERO_ACC(acc);
        gemm32h(acc, BHcur, Wa, lane, wm, wn);

        #pragma unroll
        for (int nt=0;nt<4;nt++){
            cacc[nt][0] += sigf(xfv[nt][0] + acc[nt][0]) * cc0[nt].x;
            cacc[nt][1] += sigf(xfv[nt][1] + acc[nt][1]) * cc0[nt].y;
            cacc[nt][2] += sigf(xfv[nt][2] + acc[nt][2]) * cc1[nt].x;
            cacc[nt][3] += sigf(xfv[nt][3] + acc[nt][3]) * cc1[nt].y;
        }

        if (k+2 <= 7) { CP_WAIT(0); }                // ch(k+2) staged
        __syncthreads();                             // BHnxt visible; BHcur free; staging sync
    }

    // ---- gate prologue: hs -> HSH (fp16); start weight pipeline ----------
    #pragma unroll
    for (int nt=0;nt<4;nt++){
        int C0 = wn*32 + nt*8 + 2*r;
        int ckh = C0>>3, inh = (C0&7)<<1;
        *reinterpret_cast<__half2*>(smem + OFF_HSH + SWH(Rr,   ckh) + inh) = __floats2half2_rn(hs[nt][0], hs[nt][1]);
        *reinterpret_cast<__half2*>(smem + OFF_HSH + SWH(Rr+8, ckh) + inh) = __floats2half2_rn(hs[nt][2], hs[nt][3]);
    }
    cpa_w(Wa, wimg[2], tid); CP_COMMIT();            // GW0: Wu (Wa free after last sync)
    cpa_w(WP, wimg[3], tid); CP_COMMIT();            // GW1: Uu (staging region free)

    const float* bs[3] = {bu, bi, bo};

    // ---- phase 3: 6 weight steps (Wu,Uu,Wi,Ui,Wo,Uo), 2-deep pipeline -----
    #pragma unroll 1
    for (int j=0;j<6;j++){
        const uint32_t buf = (j&1) ? WP : Wa;
        if (j<5) { CP_WAIT(1); } else { CP_WAIT(0); }
        __syncthreads();                             // weight j visible (+HSH at j=0)
        if ((j&1)==0){
            ZERO_ACC(acc);
            gemm32h(acc, XHb, buf, lane, wm, wn);    // x @ W_g
        } else {
            gemm32h(acc, HSHb, buf, lane, wm, wn);   // + hs @ U_g
        }
        __syncthreads();                             // buf free
        if (j+2 < 6){ cpa_w(buf, wimg[2 + j + 2], tid); CP_COMMIT(); }

        if (j&1){
            const int gate = j>>1;
            const float* bp = bs[gate];
            #pragma unroll
            for (int nt=0;nt<4;nt++){
                int C0 = wn*32 + nt*8 + 2*r;
                float2 bv = *reinterpret_cast<const float2*>(bp + C0);
                float p0 = acc[nt][0] + bv.x;
                float p1 = acc[nt][1] + bv.y;
                float p2 = acc[nt][2] + bv.x;
                float p3 = acc[nt][3] + bv.y;
                if (gate == 0){
                    xfv[nt][0] = tanhfast(p0);
                    xfv[nt][1] = tanhfast(p1);
                    xfv[nt][2] = tanhfast(p2);
                    xfv[nt][3] = tanhfast(p3);
                } else if (gate == 1){
                    cacc[nt][0] += sigf(p0) * xfv[nt][0];
                    cacc[nt][1] += sigf(p1) * xfv[nt][1];
                    cacc[nt][2] += sigf(p2) * xfv[nt][2];
                    cacc[nt][3] += sigf(p3) * xfv[nt][3];
                } else {
                    float c0 = cacc[nt][0], c1 = cacc[nt][1];
                    float c2 = cacc[nt][2], c3 = cacc[nt][3];
                    float h0 = sigf(p0) * tanhfast(c0);
                    float h1 = sigf(p1) * tanhfast(c1);
                    float h2 = sigf(p2) * tanhfast(c2);
                    float h3 = sigf(p3) * tanhfast(c3);
                    float* outh = out;
                    float* outc = out + (size_t)N*128;
                    *reinterpret_cast<float2*>(outh + (size_t) Rg   *128 + C0) = make_float2(h0,h1);
                    *reinterpret_cast<float2*>(outh + (size_t)(Rg+8)*128 + C0) = make_float2(h2,h3);
                    *reinterpret_cast<float2*>(outc + (size_t) Rg   *128 + C0) = make_float2(c0,c1);
                    *reinterpret_cast<float2*>(outc + (size_t)(Rg+8)*128 + C0) = make_float2(c2,c3);
                }
            }
        }
    }
}

extern "C" void kernel_launch(void* const* d_in, const int* in_sizes, int n_in,
                              void* d_out, int out_size)
{
    const float* x       = (const float*)d_in[0];
    const float* child_h = (const float*)d_in[1];
    const float* child_c = (const float*)d_in[2];
    const float* Wi = (const float*)d_in[3];
    const float* bi = (const float*)d_in[4];
    const float* Ui = (const float*)d_in[5];
    const float* Wo = (const float*)d_in[6];
    const float* bo = (const float*)d_in[7];
    const float* Uo = (const float*)d_in[8];
    const float* Wu = (const float*)d_in[9];
    const float* bu = (const float*)d_in[10];
    const float* Uu = (const float*)d_in[11];
    const float* Wf = (const float*)d_in[12];
    const float* bf = (const float*)d_in[13];
    const float* Uf = (const float*)d_in[14];
    float* out = (float*)d_out;

    int N = in_sizes[0] / 128;
    int blocks = N / ROWS;

    prep_weights<<<8, 256>>>(Wf, Uf, Wu, Uu, Wi, Ui, Wo, Uo);

    cudaFuncSetAttribute(treelstm_kernel,
                         cudaFuncAttributeMaxDynamicSharedMemorySize, SMEM_BYTES);
    treelstm_kernel<<<blocks, THREADS, SMEM_BYTES>>>(
        x, child_h, child_c, bi, bo, bu, bf, out, N);
}